// round 14
// baseline (speedup 1.0000x reference)
#include <cuda_runtime.h>
#include <stdint.h>

// Problem constants
#define VS 64
#define DEPTH_HW 256
#define IMG_H 1024
#define IMG_W 1280
#define BATCH 8
#define OUT_PER_B (VS * VS * VS)           // 262144 voxels per batch
#define N_OUT (BATCH * OUT_PER_B)          // 2097152 floats out
#define NBW (OUT_PER_B / 32)               // 8192 bit-words per batch
#define NW  (BATCH * NBW)                  // 65536 words per replica
#define R   8                              // replicas (break hot-address atomic serialization)

// Per-batch bit grids (word address includes the batch index -- spreads the
// hot near-origin voxel mass; measured essential). 8 replicas x 256KB = 2MB.
// Zeroed at module load; the expand kernels restore zero every call, so each
// kernel_launch / graph replay starts clean. Batch b's words live in
// [b*NBW, (b+1)*NBW) -> batches 0-3 and 4-7 occupy disjoint halves, enabling
// two independent scatter->expand chains.
__device__ unsigned g_bits[R][NW];

// Scatter for 4 batches (b_base..b_base+3). One thread per non-padded pixel,
// 4096 blocks x 256 threads; warp covers a 4(y) x 8(x) tile so each
// per-batch depth load is a single 128B line. Tight inline loop
// (measured-best shape): load depth, compute voxel, REDG.OR into this warp's
// replica. At the REDG lane-throughput floor.
__global__ void __launch_bounds__(256)
vox_scatter4_kernel(const float* __restrict__ depth,   // [8,256,256]
                    const float* __restrict__ ray,     // [1280*1024, 3]
                    int b_base)
{
    const int lane = threadIdx.x & 31;
    const int wid  = threadIdx.x >> 5;            // 0..7
    const int bx   = blockIdx.x & 127;            // 128 x-tiles of width 8
    const int by   = blockIdx.x >> 7;             // 32  y-tiles of height 32

    const int y  = by * 32 + wid * 4 + (lane & 3);   // 0..1023
    const int xr = bx * 8 + (lane >> 2);             // 0..1023 (non-padded x)

    unsigned* __restrict__ bits = g_bits[((blockIdx.x << 3) + wid) & (R - 1)];

    // ray index: column-major flatten idx = x*1024 + y, x = xr + 128
    const int ridx = ((xr + 128) << 10) + y;
    const float rx = __ldg(&ray[3 * ridx + 0]);
    const float ry = __ldg(&ray[3 * ridx + 1]);
    const float rz = __ldg(&ray[3 * ridx + 2]);

    const float scale = 64.0f / 3.0f;
    const int doff = ((y >> 2) << 8) + (xr >> 2);    // depth[b, y/4, xr/4]

#pragma unroll
    for (int bb = 0; bb < 4; bb++) {
        const int b = b_base + bb;
        const float d = __ldg(&depth[b * (DEPTH_HW * DEPTH_HW) + doff]);

        // Replicate reference f32 op sequence exactly: mul, add, mul,
        // round-half-even. _rn intrinsics forbid FFMA contraction.
        const float px = __fmul_rn(rx, d);
        const float py = __fmul_rn(ry, d);
        const float pz = __fmul_rn(rz, d);

        const int ix = __float2int_rn(__fmul_rn(__fadd_rn(px, 1.5f), scale));
        const int iy = __float2int_rn(__fmul_rn(__fadd_rn(py, 1.5f), scale));
        const int iz = __float2int_rn(__fmul_rn(pz, scale));

        if (((unsigned)ix < 64u) & ((unsigned)iy < 64u) & ((unsigned)iz < 64u)) {
            const int lin = (((ix << 6) + iy) << 6) + iz;
            atomicOr(&bits[b * NBW + (lin >> 5)], 1u << (lin & 31));
        }
    }

    // Padded columns all have depth==0 -> voxel (32,32,0), lin = 133120
    // = word 4160, bit 0, for this kernel's 4 batches. Replica 0.
    if (blockIdx.x == 0 && threadIdx.x < 4) {
        atomicOr(&g_bits[0][(b_base + threadIdx.x) * NBW + 4160], 1u);
    }
}

// Expand half (words [w_base, w_base+32768) = 4 batches). Measured-best
// warp-chunk shape: each warp owns 32 consecutive words exclusively (all
// replicas). Lane l accumulates word w0+l over the 8 replicas -- every load
// is one fully-coalesced 128B line per warp. Zeroing mirrors the loads
// (exclusive ownership; loads precede stores in program order => no race).
// Output: 8 rounds; round j fetches the source word via shfl, extracts this
// lane's 4-bit nibble, writes one coalesced float4. Word w maps to output
// float4s [8w, 8w+8) since out is [B][VS^3] floats and w encodes the batch.
// Writes every output element of its half -> no separate zero pass.
__global__ void __launch_bounds__(256)
vox_expand_half_kernel(float4* __restrict__ out, int w_base)
{
    const int lane = threadIdx.x & 31;
    const int warp = (blockIdx.x * 256 + threadIdx.x) >> 5;   // 0..1023
    const int w0   = w_base + warp * 32;

    unsigned acc = 0;
#pragma unroll
    for (int r = 0; r < R; r++) acc |= g_bits[r][w0 + lane];

#pragma unroll
    for (int r = 0; r < R; r++) g_bits[r][w0 + lane] = 0u;

    const unsigned sh = (lane & 7) * 4;
#pragma unroll
    for (int j = 0; j < 8; j++) {
        const unsigned v = __shfl_sync(0xFFFFFFFFu, acc, j * 4 + (lane >> 3));
        float4 o;
        o.x = ((v >> (sh + 0)) & 1u) ? 1.0f : 0.0f;
        o.y = ((v >> (sh + 1)) & 1u) ? 1.0f : 0.0f;
        o.z = ((v >> (sh + 2)) & 1u) ? 1.0f : 0.0f;
        o.w = ((v >> (sh + 3)) & 1u) ? 1.0f : 0.0f;
        out[w0 * 8 + j * 32 + lane] = o;
    }
}

extern "C" void kernel_launch(void* const* d_in, const int* in_sizes, int n_in,
                              void* d_out, int out_size)
{
    const float* depth = (const float*)d_in[0];
    const float* ray   = (const float*)d_in[1];
    // Defensive: identify by element count (depth = 524288, ray = 3932160)
    if (n_in >= 2 && in_sizes[0] == IMG_W * IMG_H * 3) {
        ray   = (const float*)d_in[0];
        depth = (const float*)d_in[1];
    }
    float4* out = (float4*)d_out;

    // Two independent chains (disjoint g_bits halves, disjoint output halves):
    //   chain A (origin stream): scatter b=0..3  -> expand words [0, 32768)
    //   chain B (side stream):   scatter b=4..7  -> expand words [32768, 65536)
    // Captured as parallel graph branches via the standard event fork/join
    // pattern. Every call is error-checked; on any failure we fall back to
    // sequential launches on the origin stream (identical results).
    cudaStream_t s1 = 0;
    cudaEvent_t ev0 = 0, evB = 0;

    bool ok = (cudaStreamCreateWithFlags(&s1, cudaStreamNonBlocking) == cudaSuccess);
    if (ok) ok = (cudaEventCreateWithFlags(&ev0, cudaEventDisableTiming) == cudaSuccess);
    if (ok) ok = (cudaEventCreateWithFlags(&evB, cudaEventDisableTiming) == cudaSuccess);
    if (ok) ok = (cudaEventRecord(ev0, 0) == cudaSuccess);           // fork point
    if (ok) ok = (cudaStreamWaitEvent(s1, ev0, 0) == cudaSuccess);   // s1 joins capture

    if (ok) {
        // chain B on side stream
        vox_scatter4_kernel<<<4096, 256, 0, s1>>>(depth, ray, 4);
        vox_expand_half_kernel<<<128, 256, 0, s1>>>(out, 32768);
        // chain A on origin stream (runs concurrently)
        vox_scatter4_kernel<<<4096, 256>>>(depth, ray, 0);
        vox_expand_half_kernel<<<128, 256>>>(out, 0);
        // join: origin waits for chain B
        ok = (cudaEventRecord(evB, s1) == cudaSuccess);
        if (ok) ok = (cudaStreamWaitEvent(0, evB, 0) == cudaSuccess);
        if (!ok) {
            // Join failed: guarantee completeness by re-running chain B's
            // kernels on the origin stream (idempotent: bit-OR scatter +
            // expand that rewrites/zeroes the same half).
            cudaGetLastError();
            vox_scatter4_kernel<<<4096, 256>>>(depth, ray, 4);
            vox_expand_half_kernel<<<128, 256>>>(out, 32768);
        }
    } else {
        cudaGetLastError();   // clear residue from failed setup
        vox_scatter4_kernel<<<4096, 256>>>(depth, ray, 0);
        vox_scatter4_kernel<<<4096, 256>>>(depth, ray, 4);
        vox_expand_half_kernel<<<128, 256>>>(out, 0);
        vox_expand_half_kernel<<<128, 256>>>(out, 32768);
    }

    // Cleanup only when demonstrably NOT capturing (destroying a stream that
    // participated in an active capture would invalidate the capture).
    cudaStreamCaptureStatus st;
    if (cudaStreamIsCapturing(0, &st) == cudaSuccess &&
        st == cudaStreamCaptureStatusNone) {
        if (s1)  cudaStreamDestroy(s1);
        if (ev0) cudaEventDestroy(ev0);
        if (evB) cudaEventDestroy(evB);
    }
    cudaGetLastError();   // leave no sticky error for the harness
}